// round 10
// baseline (speedup 1.0000x reference)
#include <cuda_runtime.h>
#include <cuda_bf16.h>
#include <cstdint>

#define VOCAB   100000
#define BATCH   32
#define CAND    32768
#define ENCD    1024
#define HID     512
#define TOK     256

// ---------------- scratch ----------------
__device__ __align__(16) float g_h[BATCH * HID];
__device__ __align__(16) __nv_bfloat16 g_qh[BATCH * TOK];   // [b][d] hi split
__device__ __align__(16) __nv_bfloat16 g_ql[BATCH * TOK];   // [b][d] lo split
__device__ __align__(16) float g_P[(size_t)VOCAB * BATCH];  // [t][b]

// mma.sync m16n8k16 row.col f32 += bf16 * bf16  (base-target PTX, sm_80+)
static __device__ __forceinline__ void mma16816(float c[4],
                                                const uint32_t a[4],
                                                const uint32_t b[2]) {
    asm volatile(
        "mma.sync.aligned.m16n8k16.row.col.f32.bf16.bf16.f32 "
        "{%0,%1,%2,%3}, {%4,%5,%6,%7}, {%8,%9}, {%0,%1,%2,%3};"
        : "+f"(c[0]), "+f"(c[1]), "+f"(c[2]), "+f"(c[3])
        : "r"(a[0]), "r"(a[1]), "r"(a[2]), "r"(a[3]), "r"(b[0]), "r"(b[1]));
}

// fp32 pair -> bf16x2 hi + bf16x2 lo (exact residual). x -> low 16.
static __device__ __forceinline__ void cvt_split(float x, float y,
                                                 uint32_t& hi, uint32_t& lo) {
    asm("cvt.rn.bf16x2.f32 %0, %1, %2;" : "=r"(hi) : "f"(y), "f"(x));
    float hx = __uint_as_float(hi << 16);
    float hy = __uint_as_float(hi & 0xFFFF0000u);
    float rx = x - hx, ry = y - hy;
    asm("cvt.rn.bf16x2.f32 %0, %1, %2;" : "=r"(lo) : "f"(ry), "f"(rx));
}

static __device__ __forceinline__ uint32_t smem_u32(const void* p) {
    return (uint32_t)__cvta_generic_to_shared(p);
}
static __device__ __forceinline__ void cp16(uint32_t dst, const void* src) {
    asm volatile("cp.async.cg.shared.global [%0], [%1], 16;"
                 :: "r"(dst), "l"(src) : "memory");
}

// ---------------------------------------------------------------------------
// K1: h[b][j] = gelu(enc[b] . W1[j] + b1[j])
// ---------------------------------------------------------------------------
__global__ void k1_hidden(const float* __restrict__ enc,
                          const float* __restrict__ W1,
                          const float* __restrict__ b1) {
    __shared__ float es[4 * ENCD];
    const int tid = threadIdx.x;
    const int bb0 = blockIdx.y * 4;

    const float4* enc4 = (const float4*)enc;
    float4* es4 = (float4*)es;
#pragma unroll
    for (int i = 0; i < 8; i++) {
        int f4 = i * 128 + tid;
        int r = f4 >> 8, k4 = f4 & 255;
        es4[f4] = enc4[(bb0 + r) * 256 + k4];
    }
    __syncthreads();

    const int w = tid >> 5, lane = tid & 31;
    const float4* W14 = (const float4*)W1;

    for (int jj = 0; jj < 8; jj++) {
        int j = blockIdx.x * 32 + w * 8 + jj;
        float acc[4] = {0.f, 0.f, 0.f, 0.f};
#pragma unroll
        for (int i = 0; i < 8; i++) {
            float4 wv = W14[j * 256 + i * 32 + lane];
#pragma unroll
            for (int bbi = 0; bbi < 4; bbi++) {
                float4 ev = es4[bbi * 256 + i * 32 + lane];
                acc[bbi] += wv.x * ev.x + wv.y * ev.y + wv.z * ev.z + wv.w * ev.w;
            }
        }
#pragma unroll
        for (int bbi = 0; bbi < 4; bbi++) {
            float v = acc[bbi];
#pragma unroll
            for (int off = 16; off > 0; off >>= 1)
                v += __shfl_xor_sync(0xFFFFFFFFu, v, off);
            if (lane == 0) {
                float x = v + b1[j];
                float g = 0.5f * x * (1.0f + erff(x * 0.70710678118654752f));
                g_h[(bb0 + bbi) * HID + j] = g;
            }
        }
    }
}

// ---------------------------------------------------------------------------
// K2: q[b][d] = h[b] . W2[d]; store as bf16 hi/lo splits, row-major [b][d]
// ---------------------------------------------------------------------------
__global__ void k2_query(const float* __restrict__ W2) {
    __shared__ float hs[4 * HID];
    const int tid = threadIdx.x;
    const int bb0 = blockIdx.y * 4;

    const float4* h4 = (const float4*)g_h;
    float4* hs4 = (float4*)hs;
#pragma unroll
    for (int i = 0; i < 4; i++) {
        int f4 = i * 128 + tid;
        int r = f4 >> 7, k4 = f4 & 127;
        hs4[f4] = h4[(bb0 + r) * 128 + k4];
    }
    __syncthreads();

    const int w = tid >> 5, lane = tid & 31;
    const float4* W24 = (const float4*)W2;

    for (int dd = 0; dd < 8; dd++) {
        int d = blockIdx.x * 32 + w * 8 + dd;
        float acc[4] = {0.f, 0.f, 0.f, 0.f};
#pragma unroll
        for (int i = 0; i < 4; i++) {
            float4 wv = W24[d * 128 + i * 32 + lane];
#pragma unroll
            for (int bbi = 0; bbi < 4; bbi++) {
                float4 hv = hs4[bbi * 128 + i * 32 + lane];
                acc[bbi] += wv.x * hv.x + wv.y * hv.y + wv.z * hv.z + wv.w * hv.w;
            }
        }
#pragma unroll
        for (int bbi = 0; bbi < 4; bbi++) {
            float v = acc[bbi];
#pragma unroll
            for (int off = 16; off > 0; off >>= 1)
                v += __shfl_xor_sync(0xFFFFFFFFu, v, off);
            if (lane == 0) {
                int b = bb0 + bbi;
                __nv_bfloat16 h = __float2bfloat16(v);
                g_qh[b * TOK + d] = h;
                g_ql[b * TOK + d] = __float2bfloat16(v - __bfloat162float(h));
            }
        }
    }
}

// ---------------------------------------------------------------------------
// K3: P[t][b] = tok_emb[t] . q[b], mma.sync bf16 3-pass split,
//     per-warp cp.async triple-buffered pipeline. 256 thr / 8 warps,
//     M=128/block (16 rows/warp), K in 16 chunks of 16.
//     smem: q hi/lo padded (33792 B) + per-warp A bufs 3 x 16 x 24 floats.
// ---------------------------------------------------------------------------
#define QROW_W 132                       // q row pitch in words (conflict-free)
#define AP     24                        // A row pitch in floats (conflict-free)
#define ABUF_W (16 * AP)                 // words per A buffer (384)
#define AWARP_W (3 * ABUF_W)             // words per warp (1152)
#define SMEM_W (2 * 32 * QROW_W + 8 * AWARP_W)   // 17664 words = 70656 B

__global__ void __launch_bounds__(256, 3) k3_mma(const float* __restrict__ tok) {
    extern __shared__ uint32_t sm[];
    uint32_t* qh = sm;
    uint32_t* ql = sm + 32 * QROW_W;

    const int tid  = threadIdx.x;
    const int warp = tid >> 5, lane = tid & 31;
    const int gr   = lane >> 2;           // fragment row group 0..7
    const int kq   = lane & 3;            // fragment k quarter 0..3

    float* aw = (float*)(sm + 2 * 32 * QROW_W) + warp * AWARP_W;

    // Stage q hi/lo (2048 uint2 each over 8 iters of 256 thr)
    {
        const uint2* gq = (const uint2*)g_qh;
        const uint2* gl = (const uint2*)g_ql;
#pragma unroll
        for (int i = 0; i < 8; i++) {
            int idx2 = i * 256 + tid;
            int n = idx2 >> 6;
            int k2 = (idx2 & 63) * 2;
            *(uint2*)&qh[n * QROW_W + k2] = gq[idx2];
            *(uint2*)&ql[n * QROW_W + k2] = gl[idx2];
        }
    }
    __syncthreads();

    const int r0 = blockIdx.x * 128 + warp * 16;

    // cp.async lane mapping: transfers t = lane (+32): row = t>>2, colgroup = t&3
    const int rowi0 = lane >> 2;          // 0..7
    const int rowi1 = 8 + (lane >> 2);    // 8..15
    const int cg    = lane & 3;
    int grow0 = r0 + rowi0; if (grow0 > VOCAB - 1) grow0 = VOCAB - 1;
    int grow1 = r0 + rowi1; if (grow1 > VOCAB - 1) grow1 = VOCAB - 1;
    const float* src0 = tok + (size_t)grow0 * 256 + cg * 4;
    const float* src1 = tok + (size_t)grow1 * 256 + cg * 4;
    const uint32_t dst0 = smem_u32(aw + rowi0 * AP + cg * 4);
    const uint32_t dst1 = smem_u32(aw + rowi1 * AP + cg * 4);
    const uint32_t BUF_B = ABUF_W * 4;    // 1536 bytes

    // Prologue: prefetch chunks 0 and 1
#pragma unroll
    for (int c = 0; c < 2; c++) {
        cp16(dst0 + c * BUF_B, src0 + c * 16);
        cp16(dst1 + c * BUF_B, src1 + c * 16);
        asm volatile("cp.async.commit_group;" ::: "memory");
    }

    float acc[4][4];
#pragma unroll
    for (int nt = 0; nt < 4; nt++)
#pragma unroll
        for (int r = 0; r < 4; r++) acc[nt][r] = 0.f;

#pragma unroll 1
    for (int ch = 0; ch < 16; ch++) {
        asm volatile("cp.async.wait_group 1;" ::: "memory");
        __syncwarp();

        // Prefetch ch+2 (empty commit at tail keeps group count uniform)
        if (ch + 2 < 16) {
            uint32_t bo = ((ch + 2) % 3) * BUF_B;
            cp16(dst0 + bo, src0 + (ch + 2) * 16);
            cp16(dst1 + bo, src1 + (ch + 2) * 16);
        }
        asm volatile("cp.async.commit_group;" ::: "memory");

        // Consume chunk ch
        const float* ab = aw + (ch % 3) * ABUF_W;
        float2 v0 = *(const float2*)&ab[gr * AP + kq * 2];
        float2 v1 = *(const float2*)&ab[(gr + 8) * AP + kq * 2];
        float2 v2 = *(const float2*)&ab[gr * AP + kq * 2 + 8];
        float2 v3 = *(const float2*)&ab[(gr + 8) * AP + kq * 2 + 8];
        uint32_t fah[4], fal[4];
        cvt_split(v0.x, v0.y, fah[0], fal[0]);
        cvt_split(v1.x, v1.y, fah[1], fal[1]);
        cvt_split(v2.x, v2.y, fah[2], fal[2]);
        cvt_split(v3.x, v3.y, fah[3], fal[3]);

        const int qw = ch * 8 + kq;
#pragma unroll
        for (int nt = 0; nt < 4; nt++) {
            uint32_t bh[2], bl[2];
            int w0 = (nt * 8 + gr) * QROW_W + qw;
            bh[0] = qh[w0]; bh[1] = qh[w0 + 4];
            bl[0] = ql[w0]; bl[1] = ql[w0 + 4];
            mma16816(acc[nt], fah, bh);
            mma16816(acc[nt], fah, bl);
            mma16816(acc[nt], fal, bh);
        }
    }

    // Epilogue: c0,c1 -> P[r0+gr][nt*8+kq*2..+1]; c2,c3 -> row+8
    int ta = r0 + gr, tb = ta + 8;
#pragma unroll
    for (int nt = 0; nt < 4; nt++) {
        int colp = nt * 8 + kq * 2;
        if (ta < VOCAB)
            *(float2*)&g_P[(size_t)ta * 32 + colp] = make_float2(acc[nt][0], acc[nt][1]);
        if (tb < VOCAB)
            *(float2*)&g_P[(size_t)tb * 32 + colp] = make_float2(acc[nt][2], acc[nt][3]);
    }
}

// ---------------------------------------------------------------------------
// K4: logits[b][c] = P[cand[b][c]][b], int4-vectorized (4 c per thread)
// ---------------------------------------------------------------------------
__global__ void k4_gather(const int4* __restrict__ cand,
                          float4* __restrict__ out) {
    int g = blockIdx.x * 256 + threadIdx.x;      // 262144 total
    int4 c = __ldcs(&cand[g]);
    int b = g >> 13;                             // 8192 int4 per batch row
    int t0 = c.x, t1 = c.y, t2 = c.z, t3 = c.w;
    t0 = (t0 < 0) ? 0 : (t0 >= VOCAB ? VOCAB - 1 : t0);
    t1 = (t1 < 0) ? 0 : (t1 >= VOCAB ? VOCAB - 1 : t1);
    t2 = (t2 < 0) ? 0 : (t2 >= VOCAB ? VOCAB - 1 : t2);
    t3 = (t3 < 0) ? 0 : (t3 >= VOCAB ? VOCAB - 1 : t3);
    float4 v;
    v.x = g_P[(size_t)t0 * 32 + b];
    v.y = g_P[(size_t)t1 * 32 + b];
    v.z = g_P[(size_t)t2 * 32 + b];
    v.w = g_P[(size_t)t3 * 32 + b];
    out[g] = v;
}

// ---------------------------------------------------------------------------
extern "C" void kernel_launch(void* const* d_in, const int* in_sizes, int n_in,
                              void* d_out, int out_size) {
    const float* enc  = (const float*)d_in[0];
    const int*   cand = (const int*)d_in[1];
    const float* tok  = (const float*)d_in[2];
    const float* W1   = (const float*)d_in[3];
    const float* b1   = (const float*)d_in[4];
    const float* W2   = (const float*)d_in[5];
    float* out = (float*)d_out;

    cudaFuncSetAttribute(k3_mma, cudaFuncAttributeMaxDynamicSharedMemorySize, SMEM_W * 4);

    k1_hidden<<<dim3(16, 8), 128>>>(enc, W1, b1);
    k2_query<<<dim3(8, 8), 128>>>(W2);
    k3_mma<<<(VOCAB + 127) / 128, 256, SMEM_W * 4>>>(tok);
    k4_gather<<<1024, 256>>>((const int4*)cand, (float4*)out);
}

// round 14
// speedup vs baseline: 1.0373x; 1.0373x over previous
#include <cuda_runtime.h>
#include <cuda_bf16.h>
#include <cuda_fp16.h>
#include <cstdint>

#define VOCAB   100000
#define BATCH   32
#define CAND    32768
#define ENCD    1024
#define HID     512
#define TOK     256

// ---------------- scratch ----------------
__device__ __align__(16) float g_h[BATCH * HID];
__device__ __align__(16) __half g_qf[BATCH * TOK];          // [b][d] fp16 q
__device__ __align__(16) float g_P[(size_t)VOCAB * BATCH];  // [t][b]

// mma.sync m16n8k16 row.col f32 += f16 * f16  (base-target PTX, sm_80+)
static __device__ __forceinline__ void mma16816h(float c[4],
                                                 const uint32_t a[4],
                                                 const uint32_t b[2]) {
    asm volatile(
        "mma.sync.aligned.m16n8k16.row.col.f32.f16.f16.f32 "
        "{%0,%1,%2,%3}, {%4,%5,%6,%7}, {%8,%9}, {%0,%1,%2,%3};"
        : "+f"(c[0]), "+f"(c[1]), "+f"(c[2]), "+f"(c[3])
        : "r"(a[0]), "r"(a[1]), "r"(a[2]), "r"(a[3]), "r"(b[0]), "r"(b[1]));
}

// pack two fp32 into f16x2: x -> low half, y -> high half
static __device__ __forceinline__ uint32_t cvt_f16x2(float x, float y) {
    uint32_t r;
    asm("cvt.rn.f16x2.f32 %0, %1, %2;" : "=r"(r) : "f"(y), "f"(x));
    return r;
}

static __device__ __forceinline__ uint32_t smem_u32(const void* p) {
    return (uint32_t)__cvta_generic_to_shared(p);
}
static __device__ __forceinline__ void cp16(uint32_t dst, const void* src) {
    asm volatile("cp.async.cg.shared.global [%0], [%1], 16;"
                 :: "r"(dst), "l"(src) : "memory");
}

// ---------------------------------------------------------------------------
// K1: h[b][j] = gelu(enc[b] . W1[j] + b1[j])
// ---------------------------------------------------------------------------
__global__ void k1_hidden(const float* __restrict__ enc,
                          const float* __restrict__ W1,
                          const float* __restrict__ b1) {
    __shared__ float es[4 * ENCD];
    const int tid = threadIdx.x;
    const int bb0 = blockIdx.y * 4;

    const float4* enc4 = (const float4*)enc;
    float4* es4 = (float4*)es;
#pragma unroll
    for (int i = 0; i < 8; i++) {
        int f4 = i * 128 + tid;
        int r = f4 >> 8, k4 = f4 & 255;
        es4[f4] = enc4[(bb0 + r) * 256 + k4];
    }
    __syncthreads();

    const int w = tid >> 5, lane = tid & 31;
    const float4* W14 = (const float4*)W1;

    for (int jj = 0; jj < 8; jj++) {
        int j = blockIdx.x * 32 + w * 8 + jj;
        float acc[4] = {0.f, 0.f, 0.f, 0.f};
#pragma unroll
        for (int i = 0; i < 8; i++) {
            float4 wv = W14[j * 256 + i * 32 + lane];
#pragma unroll
            for (int bbi = 0; bbi < 4; bbi++) {
                float4 ev = es4[bbi * 256 + i * 32 + lane];
                acc[bbi] += wv.x * ev.x + wv.y * ev.y + wv.z * ev.z + wv.w * ev.w;
            }
        }
#pragma unroll
        for (int bbi = 0; bbi < 4; bbi++) {
            float v = acc[bbi];
#pragma unroll
            for (int off = 16; off > 0; off >>= 1)
                v += __shfl_xor_sync(0xFFFFFFFFu, v, off);
            if (lane == 0) {
                float x = v + b1[j];
                float g = 0.5f * x * (1.0f + erff(x * 0.70710678118654752f));
                g_h[(bb0 + bbi) * HID + j] = g;
            }
        }
    }
}

// ---------------------------------------------------------------------------
// K2: q[b][d] = h[b] . W2[d]; store as fp16, row-major [b][d]
// ---------------------------------------------------------------------------
__global__ void k2_query(const float* __restrict__ W2) {
    __shared__ float hs[4 * HID];
    const int tid = threadIdx.x;
    const int bb0 = blockIdx.y * 4;

    const float4* h4 = (const float4*)g_h;
    float4* hs4 = (float4*)hs;
#pragma unroll
    for (int i = 0; i < 4; i++) {
        int f4 = i * 128 + tid;
        int r = f4 >> 7, k4 = f4 & 127;
        hs4[f4] = h4[(bb0 + r) * 128 + k4];
    }
    __syncthreads();

    const int w = tid >> 5, lane = tid & 31;
    const float4* W24 = (const float4*)W2;

    for (int dd = 0; dd < 8; dd++) {
        int d = blockIdx.x * 32 + w * 8 + dd;
        float acc[4] = {0.f, 0.f, 0.f, 0.f};
#pragma unroll
        for (int i = 0; i < 4; i++) {
            float4 wv = W24[d * 128 + i * 32 + lane];
#pragma unroll
            for (int bbi = 0; bbi < 4; bbi++) {
                float4 hv = hs4[bbi * 128 + i * 32 + lane];
                acc[bbi] += wv.x * hv.x + wv.y * hv.y + wv.z * hv.z + wv.w * hv.w;
            }
        }
#pragma unroll
        for (int bbi = 0; bbi < 4; bbi++) {
            float v = acc[bbi];
#pragma unroll
            for (int off = 16; off > 0; off >>= 1)
                v += __shfl_xor_sync(0xFFFFFFFFu, v, off);
            if (lane == 0)
                g_qf[(bb0 + bbi) * TOK + d] = __float2half_rn(v);
        }
    }
}

// ---------------------------------------------------------------------------
// K3: P[t][b] = tok_emb[t] . q[b], SINGLE-PASS fp16 mma.sync.
//   256 thr / 8 warps, M=128/block (16 rows/warp), K in 16 chunks of 16.
//   Per-warp cp.async triple-buffered A staging (fp32), fp32->f16x2 cvt in regs.
//   smem: q fp16 padded rows (16896 B) + per-warp A bufs 3 x 16 x 24 floats.
// ---------------------------------------------------------------------------
#define QROW_W 132                       // words per q row (256 f16 = 128 w + 4 pad)
#define AP     24                        // A row pitch in floats
#define ABUF_W (16 * AP)                 // 384 words per A buffer
#define AWARP_W (3 * ABUF_W)             // 1152 words per warp
#define SMEM_W (32 * QROW_W + 8 * AWARP_W)   // 4224 + 9216 = 13440 w = 53760 B

__global__ void __launch_bounds__(256, 4) k3_mma(const float* __restrict__ tok) {
    extern __shared__ uint32_t sm[];
    uint32_t* qf = sm;                           // fp16-pair words

    const int tid  = threadIdx.x;
    const int warp = tid >> 5, lane = tid & 31;
    const int gr   = lane >> 2;           // fragment row group 0..7
    const int kq   = lane & 3;            // fragment k quarter 0..3

    float* aw = (float*)(sm + 32 * QROW_W) + warp * AWARP_W;

    // Stage q fp16 (8192 halfs = 2048 uint2 over 8 iters; 64 uint2 per row)
    {
        const uint2* gq = (const uint2*)g_qf;
#pragma unroll
        for (int i = 0; i < 8; i++) {
            int idx2 = i * 256 + tid;            // 0..2047
            int n = idx2 >> 6;                   // b row
            int j = idx2 & 63;
            *(uint2*)&qf[n * QROW_W + j * 2] = gq[idx2];
        }
    }
    __syncthreads();

    const int r0 = blockIdx.x * 128 + warp * 16;

    const int rowi0 = lane >> 2;          // 0..7
    const int rowi1 = 8 + (lane >> 2);    // 8..15
    const int cg    = lane & 3;
    int grow0 = r0 + rowi0; if (grow0 > VOCAB - 1) grow0 = VOCAB - 1;
    int grow1 = r0 + rowi1; if (grow1 > VOCAB - 1) grow1 = VOCAB - 1;
    const float* src0 = tok + (size_t)grow0 * 256 + cg * 4;
    const float* src1 = tok + (size_t)grow1 * 256 + cg * 4;
    const uint32_t dst0 = smem_u32(aw + rowi0 * AP + cg * 4);
    const uint32_t dst1 = smem_u32(aw + rowi1 * AP + cg * 4);
    const uint32_t BUF_B = ABUF_W * 4;    // 1536 bytes

    // Prologue: prefetch chunks 0 and 1
#pragma unroll
    for (int c = 0; c < 2; c++) {
        cp16(dst0 + c * BUF_B, src0 + c * 16);
        cp16(dst1 + c * BUF_B, src1 + c * 16);
        asm volatile("cp.async.commit_group;" ::: "memory");
    }

    float acc[4][4];
#pragma unroll
    for (int nt = 0; nt < 4; nt++)
#pragma unroll
        for (int r = 0; r < 4; r++) acc[nt][r] = 0.f;

#pragma unroll 1
    for (int ch = 0; ch < 16; ch++) {
        asm volatile("cp.async.wait_group 1;" ::: "memory");
        __syncwarp();

        if (ch + 2 < 16) {
            uint32_t bo = ((ch + 2) % 3) * BUF_B;
            cp16(dst0 + bo, src0 + (ch + 2) * 16);
            cp16(dst1 + bo, src1 + (ch + 2) * 16);
        }
        asm volatile("cp.async.commit_group;" ::: "memory");

        // A fragments: fp32 from smem -> f16x2 in regs
        const float* ab = aw + (ch % 3) * ABUF_W;
        float2 v0 = *(const float2*)&ab[gr * AP + kq * 2];
        float2 v1 = *(const float2*)&ab[(gr + 8) * AP + kq * 2];
        float2 v2 = *(const float2*)&ab[gr * AP + kq * 2 + 8];
        float2 v3 = *(const float2*)&ab[(gr + 8) * AP + kq * 2 + 8];
        uint32_t fa[4];
        fa[0] = cvt_f16x2(v0.x, v0.y);
        fa[1] = cvt_f16x2(v1.x, v1.y);
        fa[2] = cvt_f16x2(v2.x, v2.y);
        fa[3] = cvt_f16x2(v3.x, v3.y);

        const int qw = ch * 8 + kq;
#pragma unroll
        for (int nt = 0; nt < 4; nt++) {
            uint32_t b[2];
            int w0 = (nt * 8 + gr) * QROW_W + qw;
            b[0] = qf[w0]; b[1] = qf[w0 + 4];
            mma16816h(acc[nt], fa, b);
        }
    }

    // Epilogue: c0,c1 -> P[r0+gr][nt*8+kq*2..+1]; c2,c3 -> row+8
    int ta = r0 + gr, tb = ta + 8;
#pragma unroll
    for (int nt = 0; nt < 4; nt++) {
        int colp = nt * 8 + kq * 2;
        if (ta < VOCAB)
            *(float2*)&g_P[(size_t)ta * 32 + colp] = make_float2(acc[nt][0], acc[nt][1]);
        if (tb < VOCAB)
            *(float2*)&g_P[(size_t)tb * 32 + colp] = make_float2(acc[nt][2], acc[nt][3]);
    }
}

// ---------------------------------------------------------------------------
// K4: logits[b][c] = P[cand[b][c]][b], 2x int4 per thread (MLP 8)
// ---------------------------------------------------------------------------
__global__ void k4_gather(const int4* __restrict__ cand,
                          float4* __restrict__ out) {
    int g0 = blockIdx.x * 256 + threadIdx.x;     // 0..131071
    int g1 = g0 + 131072;                        // second half
    int4 c0 = __ldcs(&cand[g0]);
    int4 c1 = __ldcs(&cand[g1]);
    int b0 = g0 >> 13, b1 = g1 >> 13;
    int t[8] = {c0.x, c0.y, c0.z, c0.w, c1.x, c1.y, c1.z, c1.w};
#pragma unroll
    for (int j = 0; j < 8; j++)
        t[j] = (t[j] < 0) ? 0 : (t[j] >= VOCAB ? VOCAB - 1 : t[j]);
    float4 v0, v1;
    v0.x = g_P[(size_t)t[0] * 32 + b0];
    v0.y = g_P[(size_t)t[1] * 32 + b0];
    v0.z = g_P[(size_t)t[2] * 32 + b0];
    v0.w = g_P[(size_t)t[3] * 32 + b0];
    v1.x = g_P[(size_t)t[4] * 32 + b1];
    v1.y = g_P[(size_t)t[5] * 32 + b1];
    v1.z = g_P[(size_t)t[6] * 32 + b1];
    v1.w = g_P[(size_t)t[7] * 32 + b1];
    out[g0] = v0;
    out[g1] = v1;
}

// ---------------------------------------------------------------------------
extern "C" void kernel_launch(void* const* d_in, const int* in_sizes, int n_in,
                              void* d_out, int out_size) {
    const float* enc  = (const float*)d_in[0];
    const int*   cand = (const int*)d_in[1];
    const float* tok  = (const float*)d_in[2];
    const float* W1   = (const float*)d_in[3];
    const float* b1   = (const float*)d_in[4];
    const float* W2   = (const float*)d_in[5];
    float* out = (float*)d_out;

    cudaFuncSetAttribute(k3_mma, cudaFuncAttributeMaxDynamicSharedMemorySize, SMEM_W * 4);

    k1_hidden<<<dim3(16, 8), 128>>>(enc, W1, b1);
    k2_query<<<dim3(8, 8), 128>>>(W2);
    k3_mma<<<(VOCAB + 127) / 128, 256, SMEM_W * 4>>>(tok);
    k4_gather<<<512, 256>>>((const int4*)cand, (float4*)out);
}